// round 11
// baseline (speedup 1.0000x reference)
#include <cuda_runtime.h>
#include <math.h>
#include <stdint.h>

#define GG 13
#define AA 5
#define CC 36
#define TT 30
#define BB 1024
#define GSQ (GG*GG)                   // 169
#define SLABS (BB*AA)                 // 5120
#define SLAB_BYTES 27716              // 41*169*4
#define CLS_OFF_B 3380                // 5*169*4, byte offset of class region
#define NBLK 444                      // 148 SMs * 3 blocks = exactly 1 wave
#define NTHR 288                      // 9 warps; warp 8 = sparse correction
#define SZ_A 688                      // align16 window covering 676B conf region
#define SZ_B_BASE 24336               // 36*169*4 (already /16)
#define STAGE_B (SZ_A + SZ_B_BASE + 16)   // 25040 B per stage
#define STAGE_F (STAGE_B/4)           // 6260 floats
#define NSTAGE 3

__device__ double       d_accum[3];
__device__ unsigned int d_count = 0;

__constant__ float c_aw[AA] = {1.08f, 3.42f, 6.63f, 9.42f, 16.62f};
__constant__ float c_ah[AA] = {1.19f, 4.41f, 11.38f, 5.11f, 10.52f};

extern __shared__ float sm[];         // NSTAGE * 6260 floats = 75120 B

__device__ __forceinline__ uint32_t smem_u32(const void* p) {
    uint32_t a;
    asm("{ .reg .u64 t; cvta.to.shared.u64 t, %1; cvt.u32.u64 %0, t; }"
        : "=r"(a) : "l"(p));
    return a;
}
__device__ __forceinline__ void mbar_init(uint32_t a) {
    asm volatile("mbarrier.init.shared.b64 [%0], 1;" :: "r"(a) : "memory");
}
__device__ __forceinline__ void mbar_expect(uint32_t a, uint32_t tx) {
    asm volatile("mbarrier.arrive.expect_tx.shared.b64 _, [%0], %1;"
                 :: "r"(a), "r"(tx) : "memory");
}
__device__ __forceinline__ void mbar_wait(uint32_t a, uint32_t ph) {
    asm volatile(
        "{\n\t.reg .pred P;\n"
        "W_%=:\n\t"
        "mbarrier.try_wait.parity.acquire.cta.shared::cta.b64 P, [%0], %1, 0x989680;\n\t"
        "@P bra.uni D_%=;\n\t"
        "bra.uni W_%=;\n\t"
        "D_%=:\n\t}"
        :: "r"(a), "r"(ph) : "memory");
}
__device__ __forceinline__ void bulk_cp(uint32_t dst, const void* src,
                                        uint32_t bytes, uint32_t mbar) {
    asm volatile(
        "cp.async.bulk.shared::cta.global.mbarrier::complete_tx::bytes "
        "[%0], [%1], %2, [%3];"
        :: "r"(dst), "l"(src), "r"(bytes), "r"(mbar) : "memory");
}

// issue both region copies for `slab` into stage st (one thread)
__device__ __forceinline__ void issue_slab(const char* predb, int slab, int st,
                                           uint32_t sm_base, uint32_t mbar) {
    size_t off = (size_t)slab * SLAB_BYTES;
    const char* srcA = predb + (off & ~(size_t)15);
    size_t offB = off + CLS_OFF_B;
    const char* srcB = predb + (offB & ~(size_t)15);
    uint32_t szB = SZ_B_BASE + (((slab + 1) & 3) ? 16u : 0u);
    mbar_expect(mbar, SZ_A + szB);
    uint32_t dst = sm_base + (uint32_t)st * STAGE_B;
    bulk_cp(dst, srcA, SZ_A, mbar);
    bulk_cp(dst + SZ_A, srcB, szB, mbar);
}

// ---------------------------------------------------------------------------
__global__ __launch_bounds__(NTHR, 3)
void yolo_kernel(const float* __restrict__ pred,
                 const float* __restrict__ target,
                 float* __restrict__ out) {
    __shared__ __align__(8) unsigned long long mbar_store[NSTAGE];
    __shared__ double red[3][9];
    __shared__ bool  is_last;

    const int tid = threadIdx.x, warp = tid >> 5, lane = tid & 31;
    const char* predb = (const char*)pred;
    const uint32_t sm_base = smem_u32(sm);
    const uint32_t mb0 = smem_u32(&mbar_store[0]);
    const uint32_t mb1 = smem_u32(&mbar_store[1]);
    const uint32_t mb2 = smem_u32(&mbar_store[2]);

    if (tid == 0) { mbar_init(mb0); mbar_init(mb1); mbar_init(mb2); }
    __syncthreads();

    const int nslab = (SLABS - 1 - blockIdx.x) / NBLK + 1;   // 11 or 12

    // prologue: fill all three stages (nslab >= 11)
    if (tid == 0) {
        issue_slab(predb, blockIdx.x,            0, sm_base, mb0);
        issue_slab(predb, blockIdx.x + NBLK,     1, sm_base, mb1);
        issue_slab(predb, blockIdx.x + 2*NBLK,   2, sm_base, mb2);
    }

    float f_coord = 0.0f, f_conf = 0.0f, f_class = 0.0f;

    // ------------- sparse correction (warp 8, runs under the copy stream) ----
    if (warp == 8) {
        #pragma unroll
        for (int j = 0; j < 3; ++j) {
            int b = blockIdx.x * 3 + j;
            if (b >= BB) break;
            int   cell = -1, cls = 0;
            float tx = 0.f, ty = 0.f, tw = 0.f, th = 0.f;
            if (lane < TT) {
                const float* tb = target + (unsigned)((b * TT + lane) * 5);
                float x = tb[0], y = tb[1], w = tb[2], h = tb[3], cl = tb[4];
                if (x + y + w + h + cl != 0.0f) {
                    float gx = x * GG, gy = y * GG, gw = w * GG, gh = h * GG;
                    int gi = (int)gx, gj = (int)gy;
                    float best = -1.0f; int bn = 0;
                    #pragma unroll
                    for (int a = 0; a < AA; ++a) {
                        float inter = fminf(gw, c_aw[a]) * fminf(gh, c_ah[a]);
                        float uni   = gw * gh + c_aw[a] * c_ah[a] - inter;
                        float iou   = inter / (uni + 1e-16f);
                        if (iou > best) { best = iou; bn = a; }
                    }
                    cell = (bn * GG + gj) * GG + gi;
                    cls  = (int)cl;
                    tx = gx - (float)gi;  ty = gy - (float)gj;
                    tw = __logf(gw / c_aw[bn] + 1e-16f);
                    th = __logf(gh / c_ah[bn] + 1e-16f);
                }
            }
            int  minc   = cls;
            bool winner = (cell >= 0);
            #pragma unroll
            for (int jj = 0; jj < TT; ++jj) {
                int oc   = __shfl_sync(0xFFFFFFFF, cell, jj);
                int ocls = __shfl_sync(0xFFFFFFFF, cls,  jj);
                if (cell >= 0 && oc == cell) {
                    minc = min(minc, ocls);
                    if (jj > lane) winner = false;
                }
            }
            if (winner) {
                int a = cell / GSQ;
                int s = cell - a * GSQ;
                const float* base =
                    pred + (unsigned)((b * AA + a) * (SLAB_BYTES/4) + s);
                float x0 = __ldg(base);
                float sg = 1.0f / (1.0f + __expf(-x0));
                float eo = 5.0f * (sg - 1.0f);
                f_conf += eo * eo - sg * sg;
                float p1 = __ldg(base + 1 * GSQ);
                float p2 = __ldg(base + 2 * GSQ);
                float p3 = __ldg(base + 3 * GSQ);
                float p4 = __ldg(base + 4 * GSQ);
                float q1 = p1 - tx, q2 = p2 - ty, q3 = p3 - tw, q4 = p4 - th;
                f_coord += q1*q1 + q2*q2 + q3*q3 + q4*q4;
                float x_lbl0 = __ldg(base + 5 * GSQ);
                float x_lbl  = __ldg(base + (5 + minc) * GSQ);
                f_class += x_lbl0 - x_lbl;
            }
        }
    }

    // ------------- depth-3 pipelined slab loop -------------------------------
    int ph0 = 0, ph1 = 0, ph2 = 0;
    int st = 0;
    for (int k = 0; k < nslab; ++k) {
        int slab = blockIdx.x + k * NBLK;

        uint32_t mb;
        if (st == 0)      { mb = mb0; mbar_wait(mb0, ph0); ph0 ^= 1; }
        else if (st == 1) { mb = mb1; mbar_wait(mb1, ph1); ph1 ^= 1; }
        else              { mb = mb2; mbar_wait(mb2, ph2); ph2 ^= 1; }

        if (tid < GSQ) {
            const float* A  = sm + st * STAGE_F + (slab & 3);
            const float* Bp = sm + st * STAGE_F + (SZ_A/4) + ((slab + 1) & 3);

            float x0 = A[tid];
            float sg = 1.0f / (1.0f + __expf(-x0));
            f_conf += sg * sg;

            float v5 = Bp[tid];
            float S0 = 0.0f, S1 = 0.0f;
            #pragma unroll
            for (int c = 0; c < CC; c += 2) {
                S0 += __expf(Bp[c * GSQ + tid]);
                S1 += __expf(Bp[(c + 1) * GSQ + tid]);
            }
            f_class += __logf(S0 + S1) - v5;
        }
        __syncthreads();                       // all readers done with stage st
        if (tid == 0 && k + NSTAGE < nslab)
            issue_slab(predb, blockIdx.x + (k + NSTAGE) * NBLK, st, sm_base, mb);

        st = (st == NSTAGE - 1) ? 0 : st + 1;
    }

    // ------------- block reduction (float warp, double block) ----------------
    #pragma unroll
    for (int off = 16; off > 0; off >>= 1) {
        f_coord += __shfl_down_sync(0xFFFFFFFF, f_coord, off);
        f_conf  += __shfl_down_sync(0xFFFFFFFF, f_conf,  off);
        f_class += __shfl_down_sync(0xFFFFFFFF, f_class, off);
    }
    if (lane == 0) {
        red[0][warp] = (double)f_coord;
        red[1][warp] = (double)f_conf;
        red[2][warp] = (double)f_class;
    }
    __syncthreads();
    if (warp == 0) {
        double c0 = (lane < 9) ? red[0][lane] : 0.0;
        double c1 = (lane < 9) ? red[1][lane] : 0.0;
        double c2 = (lane < 9) ? red[2][lane] : 0.0;
        #pragma unroll
        for (int off = 8; off > 0; off >>= 1) {
            c0 += __shfl_down_sync(0xFFFFFFFF, c0, off);
            c1 += __shfl_down_sync(0xFFFFFFFF, c1, off);
            c2 += __shfl_down_sync(0xFFFFFFFF, c2, off);
        }
        if (lane == 0) {
            if (c0 != 0.0) atomicAdd(&d_accum[0], c0);
            atomicAdd(&d_accum[1], c1);
            atomicAdd(&d_accum[2], c2);
        }
    }

    // ------------- last-block finalize ---------------------------------------
    if (tid == 0) {
        __threadfence();
        unsigned int prev = atomicAdd(&d_count, 1u);
        is_last = (prev == NBLK - 1);
    }
    __syncthreads();
    if (is_last && tid == 0) {
        double coord = d_accum[0] / (double)BB;
        double conf  = d_accum[1] / (double)BB;
        double cls   = d_accum[2] / (double)BB;
        out[0] = (float)(coord + conf + cls);
        out[1] = (float)coord;
        out[2] = (float)conf;
        out[3] = (float)cls;
        d_accum[0] = 0.0; d_accum[1] = 0.0; d_accum[2] = 0.0;
        d_count = 0u;
    }
}

extern "C" void kernel_launch(void* const* d_in, const int* in_sizes, int n_in,
                              void* d_out, int out_size) {
    const float* pred   = (const float*)d_in[0];
    const float* target = (const float*)d_in[1];
    float* out = (float*)d_out;

    static int attr_done = 0;
    if (!attr_done) {
        cudaFuncSetAttribute(yolo_kernel,
                             cudaFuncAttributeMaxDynamicSharedMemorySize,
                             NSTAGE * STAGE_B);
        attr_done = 1;
    }
    yolo_kernel<<<NBLK, NTHR, NSTAGE * STAGE_B>>>(pred, target, out);
}

// round 12
// speedup vs baseline: 1.0533x; 1.0533x over previous
#include <cuda_runtime.h>
#include <math.h>
#include <stdint.h>

#define GG 13
#define AA 5
#define CC 36
#define TT 30
#define BB 1024
#define GSQ (GG*GG)                   // 169
#define SLABS (BB*AA)                 // 5120
#define SLAB_BYTES 27716              // 41*169*4
#define NBLK 592                      // 148 SMs * 4 blocks = exactly 1 wave
#define NTHR 288                      // 9 warps; warp 8 = sparse correction
#define STAGE_B 27744                 // 16B-aligned window covering one slab
#define STAGE_F (STAGE_B/4)           // 6936 floats
// slab partition: first 384 blocks own 9 slabs, rest own 8 (contiguous!)
#define SLAB_LO 8
#define REM 384

__device__ double       d_accum[3];
__device__ unsigned int d_count = 0;

__constant__ float c_aw[AA] = {1.08f, 3.42f, 6.63f, 9.42f, 16.62f};
__constant__ float c_ah[AA] = {1.19f, 4.41f, 11.38f, 5.11f, 10.52f};

extern __shared__ float sm[];         // 2 stages * 6936 floats = 55488 B

__device__ __forceinline__ uint32_t smem_u32(const void* p) {
    uint32_t a;
    asm("{ .reg .u64 t; cvta.to.shared.u64 t, %1; cvt.u32.u64 %0, t; }"
        : "=r"(a) : "l"(p));
    return a;
}
__device__ __forceinline__ void mbar_init(uint32_t a) {
    asm volatile("mbarrier.init.shared.b64 [%0], 1;" :: "r"(a) : "memory");
}
__device__ __forceinline__ void mbar_expect(uint32_t a, uint32_t tx) {
    asm volatile("mbarrier.arrive.expect_tx.shared.b64 _, [%0], %1;"
                 :: "r"(a), "r"(tx) : "memory");
}
__device__ __forceinline__ void mbar_wait(uint32_t a, uint32_t ph) {
    asm volatile(
        "{\n\t.reg .pred P;\n"
        "W_%=:\n\t"
        "mbarrier.try_wait.parity.acquire.cta.shared::cta.b64 P, [%0], %1, 0x989680;\n\t"
        "@P bra.uni D_%=;\n\t"
        "bra.uni W_%=;\n\t"
        "D_%=:\n\t}"
        :: "r"(a), "r"(ph) : "memory");
}
__device__ __forceinline__ void bulk_cp(uint32_t dst, const void* src,
                                        uint32_t bytes, uint32_t mbar) {
    asm volatile(
        "cp.async.bulk.shared::cta.global.mbarrier::complete_tx::bytes "
        "[%0], [%1], %2, [%3];"
        :: "r"(dst), "l"(src), "r"(bytes), "r"(mbar) : "memory");
}

// issue one full-slab copy (16B-aligned window) into stage st
__device__ __forceinline__ void issue_slab(const char* predb, int slab, int st,
                                           uint32_t sm_base, uint32_t mbar) {
    size_t beg = (size_t)slab * SLAB_BYTES;
    size_t end = beg + SLAB_BYTES;
    size_t src = beg & ~(size_t)15;
    uint32_t sz = (uint32_t)(((end + 15) & ~(size_t)15) - src);
    mbar_expect(mbar, sz);
    bulk_cp(sm_base + (uint32_t)st * STAGE_B, predb + src, sz, mbar);
}

// ---------------------------------------------------------------------------
__global__ __launch_bounds__(NTHR, 4)
void yolo_kernel(const float* __restrict__ pred,
                 const float* __restrict__ target,
                 float* __restrict__ out) {
    __shared__ __align__(8) unsigned long long mbar_store[2];
    __shared__ double red[3][9];
    __shared__ bool  is_last;

    const int tid = threadIdx.x, warp = tid >> 5, lane = tid & 31;
    const char* predb = (const char*)pred;
    const uint32_t sm_base = smem_u32(sm);
    const uint32_t mb0 = smem_u32(&mbar_store[0]);
    const uint32_t mb1 = smem_u32(&mbar_store[1]);

    if (tid == 0) { mbar_init(mb0); mbar_init(mb1); }
    __syncthreads();

    // contiguous slab range for this block
    const int bid   = blockIdx.x;
    const int s0    = bid * SLAB_LO + (bid < REM ? bid : REM);
    const int nslab = SLAB_LO + (bid < REM ? 1 : 0);      // 8 or 9

    // prologue: fill both stages
    if (tid == 0) {
        issue_slab(predb, s0,     0, sm_base, mb0);
        issue_slab(predb, s0 + 1, 1, sm_base, mb1);
    }

    float f_coord = 0.0f, f_conf = 0.0f, f_class = 0.0f;

    // ------------- sparse correction (warp 8, runs under the copy stream) ----
    if (warp == 8) {
        #pragma unroll
        for (int j = 0; j < 2; ++j) {
            int b = bid * 2 + j;
            if (b >= BB) break;
            int   cell = -1, cls = 0;
            float tx = 0.f, ty = 0.f, tw = 0.f, th = 0.f;
            if (lane < TT) {
                const float* tb = target + (unsigned)((b * TT + lane) * 5);
                float x = tb[0], y = tb[1], w = tb[2], h = tb[3], cl = tb[4];
                if (x + y + w + h + cl != 0.0f) {
                    float gx = x * GG, gy = y * GG, gw = w * GG, gh = h * GG;
                    int gi = (int)gx, gj = (int)gy;
                    float best = -1.0f; int bn = 0;
                    #pragma unroll
                    for (int a = 0; a < AA; ++a) {
                        float inter = fminf(gw, c_aw[a]) * fminf(gh, c_ah[a]);
                        float uni   = gw * gh + c_aw[a] * c_ah[a] - inter;
                        float iou   = inter / (uni + 1e-16f);
                        if (iou > best) { best = iou; bn = a; }
                    }
                    cell = (bn * GG + gj) * GG + gi;
                    cls  = (int)cl;
                    tx = gx - (float)gi;  ty = gy - (float)gj;
                    tw = __logf(gw / c_aw[bn] + 1e-16f);
                    th = __logf(gh / c_ah[bn] + 1e-16f);
                }
            }
            int  minc   = cls;
            bool winner = (cell >= 0);
            #pragma unroll
            for (int jj = 0; jj < TT; ++jj) {
                int oc   = __shfl_sync(0xFFFFFFFF, cell, jj);
                int ocls = __shfl_sync(0xFFFFFFFF, cls,  jj);
                if (cell >= 0 && oc == cell) {
                    minc = min(minc, ocls);
                    if (jj > lane) winner = false;
                }
            }
            if (winner) {
                int a = cell / GSQ;
                int s = cell - a * GSQ;
                const float* base =
                    pred + (unsigned)((b * AA + a) * (SLAB_BYTES/4) + s);
                float x0 = __ldg(base);
                float sg = 1.0f / (1.0f + __expf(-x0));
                float eo = 5.0f * (sg - 1.0f);
                f_conf += eo * eo - sg * sg;
                float p1 = __ldg(base + 1 * GSQ);
                float p2 = __ldg(base + 2 * GSQ);
                float p3 = __ldg(base + 3 * GSQ);
                float p4 = __ldg(base + 4 * GSQ);
                float q1 = p1 - tx, q2 = p2 - ty, q3 = p3 - tw, q4 = p4 - th;
                f_coord += q1*q1 + q2*q2 + q3*q3 + q4*q4;
                float x_lbl0 = __ldg(base + 5 * GSQ);
                float x_lbl  = __ldg(base + (5 + minc) * GSQ);
                f_class += x_lbl0 - x_lbl;
            }
        }
    }

    // ------------- depth-2 pipelined slab loop (contiguous stream) -----------
    int ph0 = 0, ph1 = 0;
    for (int k = 0; k < nslab; ++k) {
        int st   = k & 1;
        int slab = s0 + k;

        if (st == 0) { mbar_wait(mb0, ph0); ph0 ^= 1; }
        else         { mbar_wait(mb1, ph1); ph1 ^= 1; }

        if (tid < GSQ) {
            // head offset: (27716*slab) mod 16 = 4*(slab&3) bytes
            const float* P = sm + st * STAGE_F + (slab & 3);

            float x0 = P[tid];                       // conf channel 0
            float sg = 1.0f / (1.0f + __expf(-x0));
            f_conf += sg * sg;

            float v5 = P[5 * GSQ + tid];
            float S0 = 0.0f, S1 = 0.0f;
            #pragma unroll
            for (int c = 0; c < CC; c += 2) {
                S0 += __expf(P[(5 + c) * GSQ + tid]);
                S1 += __expf(P[(6 + c) * GSQ + tid]);
            }
            f_class += __logf(S0 + S1) - v5;
        }
        __syncthreads();                       // all readers done with stage st
        if (tid == 0 && k + 2 < nslab)
            issue_slab(predb, s0 + k + 2, st, sm_base, st == 0 ? mb0 : mb1);
    }

    // ------------- block reduction (float warp, double block) ----------------
    #pragma unroll
    for (int off = 16; off > 0; off >>= 1) {
        f_coord += __shfl_down_sync(0xFFFFFFFF, f_coord, off);
        f_conf  += __shfl_down_sync(0xFFFFFFFF, f_conf,  off);
        f_class += __shfl_down_sync(0xFFFFFFFF, f_class, off);
    }
    if (lane == 0) {
        red[0][warp] = (double)f_coord;
        red[1][warp] = (double)f_conf;
        red[2][warp] = (double)f_class;
    }
    __syncthreads();
    if (warp == 0) {
        double c0 = (lane < 9) ? red[0][lane] : 0.0;
        double c1 = (lane < 9) ? red[1][lane] : 0.0;
        double c2 = (lane < 9) ? red[2][lane] : 0.0;
        #pragma unroll
        for (int off = 8; off > 0; off >>= 1) {
            c0 += __shfl_down_sync(0xFFFFFFFF, c0, off);
            c1 += __shfl_down_sync(0xFFFFFFFF, c1, off);
            c2 += __shfl_down_sync(0xFFFFFFFF, c2, off);
        }
        if (lane == 0) {
            if (c0 != 0.0) atomicAdd(&d_accum[0], c0);
            atomicAdd(&d_accum[1], c1);
            atomicAdd(&d_accum[2], c2);
        }
    }

    // ------------- last-block finalize ---------------------------------------
    if (tid == 0) {
        __threadfence();
        unsigned int prev = atomicAdd(&d_count, 1u);
        is_last = (prev == NBLK - 1);
    }
    __syncthreads();
    if (is_last && tid == 0) {
        double coord = d_accum[0] / (double)BB;
        double conf  = d_accum[1] / (double)BB;
        double cls   = d_accum[2] / (double)BB;
        out[0] = (float)(coord + conf + cls);
        out[1] = (float)coord;
        out[2] = (float)conf;
        out[3] = (float)cls;
        d_accum[0] = 0.0; d_accum[1] = 0.0; d_accum[2] = 0.0;
        d_count = 0u;
    }
}

extern "C" void kernel_launch(void* const* d_in, const int* in_sizes, int n_in,
                              void* d_out, int out_size) {
    const float* pred   = (const float*)d_in[0];
    const float* target = (const float*)d_in[1];
    float* out = (float*)d_out;

    static int attr_done = 0;
    if (!attr_done) {
        cudaFuncSetAttribute(yolo_kernel,
                             cudaFuncAttributeMaxDynamicSharedMemorySize,
                             2 * STAGE_B);
        attr_done = 1;
    }
    yolo_kernel<<<NBLK, NTHR, 2 * STAGE_B>>>(pred, target, out);
}